// round 2
// baseline (speedup 1.0000x reference)
#include <cuda_runtime.h>

#define T 3
#define B 100000
#define D 128
#define NEG_SLOPE 0.01f

// One warp handles one (t, b) pair. Lane l owns elements [4l, 4l+4) of D.
__global__ void __launch_bounds__(256, 8)
attconv_kernel(const float* __restrict__ h_center,
               const float* __restrict__ h_neigh,
               const float* __restrict__ att_w,
               const float* __restrict__ att_b,
               float* __restrict__ out)
{
    const int t    = blockIdx.y;
    const int warp = threadIdx.x >> 5;
    const int lane = threadIdx.x & 31;
    const int b    = blockIdx.x * (blockDim.x >> 5) + warp;
    if (b >= B) return;

    // Issue all streaming loads first (maximize MLP; ptxas will front-batch).
    const size_t cbase   = ((size_t)t * B + b) * D + lane * 4;
    const size_t nstride = (size_t)B * D;
    const size_t nbase   = ((size_t)t * T) * nstride + (size_t)b * D + lane * 4;

    const float4 c4 = *reinterpret_cast<const float4*>(h_center + cbase);
    const float4 v0 = *reinterpret_cast<const float4*>(h_neigh + nbase);
    const float4 v1 = *reinterpret_cast<const float4*>(h_neigh + nbase + nstride);
    const float4 v2 = *reinterpret_cast<const float4*>(h_neigh + nbase + 2 * nstride);

    // Per-t weights: w_h = att_w[t, 0:D], w_e = att_w[t, D:2D]  (L2-resident)
    const float4 wh = *reinterpret_cast<const float4*>(att_w + (size_t)t * 2 * D + lane * 4);
    const float4 we = *reinterpret_cast<const float4*>(att_w + (size_t)t * 2 * D + D + lane * 4);
    const float bias = att_b[t];

    // Per-lane partial dot products (5 of them)
    float se0 = v0.x * we.x + v0.y * we.y + v0.z * we.z + v0.w * we.w;
    float se1 = v1.x * we.x + v1.y * we.y + v1.z * we.z + v1.w * we.w;
    float se2 = v2.x * we.x + v2.y * we.y + v2.z * we.z + v2.w * we.w;
    float sec = c4.x * we.x + c4.y * we.y + c4.z * we.z + c4.w * we.w;
    float sh  = c4.x * wh.x + c4.y * wh.y + c4.z * wh.z + c4.w * wh.w;

    // Butterfly warp reductions -> all lanes hold the full sums
    #pragma unroll
    for (int off = 16; off > 0; off >>= 1) {
        se0 += __shfl_xor_sync(0xFFFFFFFFu, se0, off);
        se1 += __shfl_xor_sync(0xFFFFFFFFu, se1, off);
        se2 += __shfl_xor_sync(0xFFFFFFFFu, se2, off);
        sec += __shfl_xor_sync(0xFFFFFFFFu, sec, off);
        sh  += __shfl_xor_sync(0xFFFFFFFFu, sh,  off);
    }

    // scores[n] = score_e[n] + score_h + bias, leaky relu, softmax over n (4 entries)
    float s0 = se0 + sh + bias;
    float s1 = se1 + sh + bias;
    float s2 = se2 + sh + bias;
    float s3 = sec + sh + bias;   // n = T is the center slot (concat order: neigh first)

    s0 = (s0 >= 0.f) ? s0 : NEG_SLOPE * s0;
    s1 = (s1 >= 0.f) ? s1 : NEG_SLOPE * s1;
    s2 = (s2 >= 0.f) ? s2 : NEG_SLOPE * s2;
    s3 = (s3 >= 0.f) ? s3 : NEG_SLOPE * s3;

    float m = fmaxf(fmaxf(s0, s1), fmaxf(s2, s3));
    float e0 = __expf(s0 - m);
    float e1 = __expf(s1 - m);
    float e2 = __expf(s2 - m);
    float e3 = __expf(s3 - m);
    float inv = 1.0f / (e0 + e1 + e2 + e3);
    e0 *= inv; e1 *= inv; e2 *= inv; e3 *= inv;

    // Weighted sum over the 4 concatenated vectors
    float4 o;
    o.x = e0 * v0.x + e1 * v1.x + e2 * v2.x + e3 * c4.x;
    o.y = e0 * v0.y + e1 * v1.y + e2 * v2.y + e3 * c4.y;
    o.z = e0 * v0.z + e1 * v1.z + e2 * v2.z + e3 * c4.z;
    o.w = e0 * v0.w + e1 * v1.w + e2 * v2.w + e3 * c4.w;

    *reinterpret_cast<float4*>(out + cbase) = o;
}

extern "C" void kernel_launch(void* const* d_in, const int* in_sizes, int n_in,
                              void* d_out, int out_size)
{
    const float* h_center = (const float*)d_in[0];
    const float* h_neigh  = (const float*)d_in[1];
    const float* att_w    = (const float*)d_in[2];
    const float* att_b    = (const float*)d_in[3];
    float* out = (float*)d_out;

    const int warps_per_block = 8;                 // 256 threads
    dim3 block(32 * warps_per_block);
    dim3 grid((B + warps_per_block - 1) / warps_per_block, T);
    attconv_kernel<<<grid, block>>>(h_center, h_neigh, att_w, att_b, out);
}

// round 3
// speedup vs baseline: 1.0038x; 1.0038x over previous
#include <cuda_runtime.h>

#define T 3
#define B 100000
#define D 128
#define NEG_SLOPE 0.01f

// One warp handles TWO adjacent (t, b) pairs: b0 = 2*slot, b1 = 2*slot+1.
// Lane l owns elements [4l, 4l+4) of D. 8 outstanding LDG.128 per warp (MLP=8),
// adjacent 512B lines per vector -> 1KB sequential streams. Streaming cache
// hints (.cs) since every line is touched exactly once.
__global__ void __launch_bounds__(256)
attconv_kernel(const float* __restrict__ h_center,
               const float* __restrict__ h_neigh,
               const float* __restrict__ att_w,
               const float* __restrict__ att_b,
               float* __restrict__ out)
{
    const int t    = blockIdx.y;
    const int warp = threadIdx.x >> 5;
    const int lane = threadIdx.x & 31;
    const int slot = blockIdx.x * (blockDim.x >> 5) + warp;
    const int b0   = slot * 2;          // B = 100000 is even: no tail
    if (b0 >= B) return;

    const size_t cbase   = ((size_t)t * B + b0) * D + lane * 4;
    const size_t nstride = (size_t)B * D;
    const size_t nbase   = ((size_t)t * T) * nstride + (size_t)b0 * D + lane * 4;

    // Front-batch all 8 streaming loads (evict-first: data is single-use).
    const float4 cA  = __ldcs(reinterpret_cast<const float4*>(h_center + cbase));
    const float4 cB  = __ldcs(reinterpret_cast<const float4*>(h_center + cbase + D));
    const float4 v0A = __ldcs(reinterpret_cast<const float4*>(h_neigh + nbase));
    const float4 v0B = __ldcs(reinterpret_cast<const float4*>(h_neigh + nbase + D));
    const float4 v1A = __ldcs(reinterpret_cast<const float4*>(h_neigh + nbase + nstride));
    const float4 v1B = __ldcs(reinterpret_cast<const float4*>(h_neigh + nbase + nstride + D));
    const float4 v2A = __ldcs(reinterpret_cast<const float4*>(h_neigh + nbase + 2 * nstride));
    const float4 v2B = __ldcs(reinterpret_cast<const float4*>(h_neigh + nbase + 2 * nstride + D));

    // Per-t weights (L2-resident, reused by every warp -> default caching).
    const float4 wh = *reinterpret_cast<const float4*>(att_w + (size_t)t * 2 * D + lane * 4);
    const float4 we = *reinterpret_cast<const float4*>(att_w + (size_t)t * 2 * D + D + lane * 4);
    const float bias = att_b[t];

    // Per-lane partial dot products: 5 per b, 10 total.
    float se0A = v0A.x*we.x + v0A.y*we.y + v0A.z*we.z + v0A.w*we.w;
    float se1A = v1A.x*we.x + v1A.y*we.y + v1A.z*we.z + v1A.w*we.w;
    float se2A = v2A.x*we.x + v2A.y*we.y + v2A.z*we.z + v2A.w*we.w;
    float secA = cA.x *we.x + cA.y *we.y + cA.z *we.z + cA.w *we.w;
    float shA  = cA.x *wh.x + cA.y *wh.y + cA.z *wh.z + cA.w *wh.w;

    float se0B = v0B.x*we.x + v0B.y*we.y + v0B.z*we.z + v0B.w*we.w;
    float se1B = v1B.x*we.x + v1B.y*we.y + v1B.z*we.z + v1B.w*we.w;
    float se2B = v2B.x*we.x + v2B.y*we.y + v2B.z*we.z + v2B.w*we.w;
    float secB = cB.x *we.x + cB.y *we.y + cB.z *we.z + cB.w *we.w;
    float shB  = cB.x *wh.x + cB.y *wh.y + cB.z *wh.z + cB.w *wh.w;

    // Butterfly warp reductions (10 independent chains).
    #pragma unroll
    for (int off = 16; off > 0; off >>= 1) {
        se0A += __shfl_xor_sync(0xFFFFFFFFu, se0A, off);
        se1A += __shfl_xor_sync(0xFFFFFFFFu, se1A, off);
        se2A += __shfl_xor_sync(0xFFFFFFFFu, se2A, off);
        secA += __shfl_xor_sync(0xFFFFFFFFu, secA, off);
        shA  += __shfl_xor_sync(0xFFFFFFFFu, shA,  off);
        se0B += __shfl_xor_sync(0xFFFFFFFFu, se0B, off);
        se1B += __shfl_xor_sync(0xFFFFFFFFu, se1B, off);
        se2B += __shfl_xor_sync(0xFFFFFFFFu, se2B, off);
        secB += __shfl_xor_sync(0xFFFFFFFFu, secB, off);
        shB  += __shfl_xor_sync(0xFFFFFFFFu, shB,  off);
    }

    // --- pair A: scores, leaky relu, softmax, blend ---
    {
        float s0 = se0A + shA + bias;
        float s1 = se1A + shA + bias;
        float s2 = se2A + shA + bias;
        float s3 = secA + shA + bias;
        s0 = (s0 >= 0.f) ? s0 : NEG_SLOPE * s0;
        s1 = (s1 >= 0.f) ? s1 : NEG_SLOPE * s1;
        s2 = (s2 >= 0.f) ? s2 : NEG_SLOPE * s2;
        s3 = (s3 >= 0.f) ? s3 : NEG_SLOPE * s3;
        float m = fmaxf(fmaxf(s0, s1), fmaxf(s2, s3));
        float e0 = __expf(s0 - m), e1 = __expf(s1 - m);
        float e2 = __expf(s2 - m), e3 = __expf(s3 - m);
        float inv = 1.0f / (e0 + e1 + e2 + e3);
        e0 *= inv; e1 *= inv; e2 *= inv; e3 *= inv;
        float4 o;
        o.x = e0*v0A.x + e1*v1A.x + e2*v2A.x + e3*cA.x;
        o.y = e0*v0A.y + e1*v1A.y + e2*v2A.y + e3*cA.y;
        o.z = e0*v0A.z + e1*v1A.z + e2*v2A.z + e3*cA.z;
        o.w = e0*v0A.w + e1*v1A.w + e2*v2A.w + e3*cA.w;
        __stcs(reinterpret_cast<float4*>(out + cbase), o);
    }

    // --- pair B ---
    {
        float s0 = se0B + shB + bias;
        float s1 = se1B + shB + bias;
        float s2 = se2B + shB + bias;
        float s3 = secB + shB + bias;
        s0 = (s0 >= 0.f) ? s0 : NEG_SLOPE * s0;
        s1 = (s1 >= 0.f) ? s1 : NEG_SLOPE * s1;
        s2 = (s2 >= 0.f) ? s2 : NEG_SLOPE * s2;
        s3 = (s3 >= 0.f) ? s3 : NEG_SLOPE * s3;
        float m = fmaxf(fmaxf(s0, s1), fmaxf(s2, s3));
        float e0 = __expf(s0 - m), e1 = __expf(s1 - m);
        float e2 = __expf(s2 - m), e3 = __expf(s3 - m);
        float inv = 1.0f / (e0 + e1 + e2 + e3);
        e0 *= inv; e1 *= inv; e2 *= inv; e3 *= inv;
        float4 o;
        o.x = e0*v0B.x + e1*v1B.x + e2*v2B.x + e3*cB.x;
        o.y = e0*v0B.y + e1*v1B.y + e2*v2B.y + e3*cB.y;
        o.z = e0*v0B.z + e1*v1B.z + e2*v2B.z + e3*cB.z;
        o.w = e0*v0B.w + e1*v1B.w + e2*v2B.w + e3*cB.w;
        __stcs(reinterpret_cast<float4*>(out + cbase + D), o);
    }
}

extern "C" void kernel_launch(void* const* d_in, const int* in_sizes, int n_in,
                              void* d_out, int out_size)
{
    const float* h_center = (const float*)d_in[0];
    const float* h_neigh  = (const float*)d_in[1];
    const float* att_w    = (const float*)d_in[2];
    const float* att_b    = (const float*)d_in[3];
    float* out = (float*)d_out;

    const int warps_per_block = 8;                  // 256 threads
    const int pairs = B / 2;                        // 50000 warp-slots per t
    dim3 block(32 * warps_per_block);
    dim3 grid((pairs + warps_per_block - 1) / warps_per_block, T);
    attconv_kernel<<<grid, block>>>(h_center, h_neigh, att_w, att_b, out);
}